// round 3
// baseline (speedup 1.0000x reference)
#include <cuda_runtime.h>
#include <math.h>

#define B_ 4
#define T_ 2048
#define C_ 1024
#define H_ 16
#define D_ 64
#define WIN_ 256

// Scratch (allocation-free rule: __device__ globals)
__device__ float g_qkv[(size_t)B_ * T_ * 3 * C_];   // [B*T, 3C]
__device__ float g_att[(size_t)B_ * T_ * C_];       // [B*T, C]

// ---------------------------------------------------------------------------
// SGEMM (NT): C[m,n] = sum_k A[m,k] * B[n,k]
// BM=BN=128, BK=8, 256 threads, 8x8 thread tile.
// ---------------------------------------------------------------------------
__global__ __launch_bounds__(256) void sgemm_nt(const float* __restrict__ A,
                                                const float* __restrict__ Bm,
                                                float* __restrict__ Cm,
                                                int M, int N, int K) {
    __shared__ float As[8][132];
    __shared__ float Bs[8][132];
    const int tid = threadIdx.x;
    const int tx = tid & 15, ty = tid >> 4;
    const int m0 = blockIdx.y * 128, n0 = blockIdx.x * 128;
    const int arow = tid >> 1, acol = (tid & 1) * 4;

    const float* Ap = A + (long)(m0 + arow) * K + acol;
    const float* Bp = Bm + (long)(n0 + arow) * K + acol;

    float acc[8][8];
#pragma unroll
    for (int i = 0; i < 8; i++)
#pragma unroll
        for (int j = 0; j < 8; j++) acc[i][j] = 0.f;

    for (int k0 = 0; k0 < K; k0 += 8) {
        float4 av = *(const float4*)(Ap + k0);
        float4 bv = *(const float4*)(Bp + k0);
        As[acol + 0][arow] = av.x; As[acol + 1][arow] = av.y;
        As[acol + 2][arow] = av.z; As[acol + 3][arow] = av.w;
        Bs[acol + 0][arow] = bv.x; Bs[acol + 1][arow] = bv.y;
        Bs[acol + 2][arow] = bv.z; Bs[acol + 3][arow] = bv.w;
        __syncthreads();
#pragma unroll
        for (int k = 0; k < 8; k++) {
            float a[8], b[8];
            *(float4*)(a)     = *(const float4*)&As[k][ty * 8];
            *(float4*)(a + 4) = *(const float4*)&As[k][ty * 8 + 4];
            *(float4*)(b)     = *(const float4*)&Bs[k][tx * 8];
            *(float4*)(b + 4) = *(const float4*)&Bs[k][tx * 8 + 4];
#pragma unroll
            for (int i = 0; i < 8; i++)
#pragma unroll
                for (int j = 0; j < 8; j++)
                    acc[i][j] += a[i] * b[j];
        }
        __syncthreads();
    }

#pragma unroll
    for (int i = 0; i < 8; i++) {
        int m = m0 + ty * 8 + i;
        float* cp = Cm + (long)m * N + n0 + tx * 8;
        *(float4*)(cp)     = make_float4(acc[i][0], acc[i][1], acc[i][2], acc[i][3]);
        *(float4*)(cp + 4) = make_float4(acc[i][4], acc[i][5], acc[i][6], acc[i][7]);
    }
}

// ---------------------------------------------------------------------------
// Sliding-window attention. Block = (q-tile of 64) x (one b,h).
// 256 threads: (tx,ty) 16x8 grid; thread owns queries ty*4..+3, dims tx*4..+3.
// Dynamic shared layout:
//   Qs[64][68]  transposed [d][qi] (pre-scaled)
//   Ks[64][68]  transposed [d][kj]
//   Vs[64][68]  [kj][d]
//   Ss[64][68]  [qi][kj]   scores -> probabilities
//   m_s[64], l_s[64], corr_s[64]
// ---------------------------------------------------------------------------
#define SROW 68
__global__ __launch_bounds__(256) void attn_kernel(const float* __restrict__ qkv,
                                                   float* __restrict__ yatt) {
    extern __shared__ float sm[];
    float* Qs = sm;                   // 64*68
    float* Ks = Qs + 64 * SROW;
    float* Vs = Ks + 64 * SROW;
    float* Ss = Vs + 64 * SROW;
    float* m_s = Ss + 64 * SROW;
    float* l_s = m_s + 64;
    float* corr_s = l_s + 64;

    const int qt = blockIdx.x, h = blockIdx.y, b = blockIdx.z;
    const int q0 = qt * 64;
    const int tid = threadIdx.x;
    const int tx = tid & 15, ty = tid >> 4;
    const float scale = 0.125f;  // 1/sqrt(64)

    // Load Q tile (transposed, scaled). 4 threads per query row.
    {
        const int qi = tid >> 2, part = tid & 3;
        const float* qp = qkv + ((long)(b * T_ + q0 + qi) * (3 * C_)) + h * D_ + part * 16;
#pragma unroll
        for (int i = 0; i < 16; i += 4) {
            float4 v = *(const float4*)(qp + i);
            Qs[(part * 16 + i + 0) * SROW + qi] = v.x * scale;
            Qs[(part * 16 + i + 1) * SROW + qi] = v.y * scale;
            Qs[(part * 16 + i + 2) * SROW + qi] = v.z * scale;
            Qs[(part * 16 + i + 3) * SROW + qi] = v.w * scale;
        }
        if (tid < 64) { m_s[tid] = -1e30f; l_s[tid] = 0.f; }
    }

    float o[4][4];
#pragma unroll
    for (int i = 0; i < 4; i++)
#pragma unroll
        for (int j = 0; j < 4; j++) o[i][j] = 0.f;

    const int kt0 = (qt >= 4) ? (qt - 4) : 0;
    for (int kt = kt0; kt <= qt; kt++) {
        __syncthreads();  // previous tile fully consumed; Q/m_s init visible
        // Load K (transposed) and V tiles
        {
            const int kj = tid >> 2, part = tid & 3;
            const float* kp = qkv + ((long)(b * T_ + kt * 64 + kj) * (3 * C_)) + C_ + h * D_ + part * 16;
            const float* vp = kp + C_;
#pragma unroll
            for (int i = 0; i < 16; i += 4) {
                float4 kv = *(const float4*)(kp + i);
                Ks[(part * 16 + i + 0) * SROW + kj] = kv.x;
                Ks[(part * 16 + i + 1) * SROW + kj] = kv.y;
                Ks[(part * 16 + i + 2) * SROW + kj] = kv.z;
                Ks[(part * 16 + i + 3) * SROW + kj] = kv.w;
                float4 vv = *(const float4*)(vp + i);
                *(float4*)&Vs[kj * SROW + part * 16 + i] = vv;
            }
        }
        __syncthreads();

        // Scores: S[qi][kj] with sliding-window mask
        {
            float s[4][4];
#pragma unroll
            for (int i = 0; i < 4; i++)
#pragma unroll
                for (int j = 0; j < 4; j++) s[i][j] = 0.f;
#pragma unroll
            for (int d = 0; d < 64; d++) {
                float a[4], c[4];
                *(float4*)a = *(const float4*)&Qs[d * SROW + ty * 4];
                *(float4*)c = *(const float4*)&Ks[d * SROW + tx * 4];
#pragma unroll
                for (int qq = 0; qq < 4; qq++)
#pragma unroll
                    for (int kk = 0; kk < 4; kk++)
                        s[qq][kk] += a[qq] * c[kk];
            }
#pragma unroll
            for (int qq = 0; qq < 4; qq++) {
                const int qg = q0 + ty * 4 + qq;
                float4 row;
                float* rp = &row.x;
#pragma unroll
                for (int kk = 0; kk < 4; kk++) {
                    const int jg = kt * 64 + tx * 4 + kk;
                    const bool valid = (jg <= qg) && (jg > qg - WIN_);
                    rp[kk] = valid ? s[qq][kk] : -1e30f;
                }
                *(float4*)&Ss[(ty * 4 + qq) * SROW + tx * 4] = row;
            }
        }
        __syncthreads();

        // Online softmax update (4 lanes per query, all in same warp)
        {
            const int qi = tid >> 2, part = tid & 3;
            float* srow = &Ss[qi * SROW + part * 16];
            float mx = -1e30f;
#pragma unroll
            for (int j = 0; j < 16; j++) mx = fmaxf(mx, srow[j]);
            mx = fmaxf(mx, __shfl_xor_sync(0xffffffffu, mx, 1));
            mx = fmaxf(mx, __shfl_xor_sync(0xffffffffu, mx, 2));
            const float m_old = m_s[qi];
            const float m_new = fmaxf(m_old, mx);
            float lsum = 0.f;
#pragma unroll
            for (int j = 0; j < 16; j++) {
                float p = __expf(srow[j] - m_new);
                srow[j] = p;
                lsum += p;
            }
            lsum += __shfl_xor_sync(0xffffffffu, lsum, 1);
            lsum += __shfl_xor_sync(0xffffffffu, lsum, 2);
            if (part == 0) {
                const float corr = __expf(m_old - m_new);
                corr_s[qi] = corr;
                l_s[qi] = l_s[qi] * corr + lsum;
                m_s[qi] = m_new;
            }
        }
        __syncthreads();

        // PV accumulate (p loads are warp broadcasts, v loads are float4)
        {
            float c[4];
#pragma unroll
            for (int qq = 0; qq < 4; qq++) c[qq] = corr_s[ty * 4 + qq];
#pragma unroll
            for (int qq = 0; qq < 4; qq++)
#pragma unroll
                for (int dd = 0; dd < 4; dd++) o[qq][dd] *= c[qq];
#pragma unroll
            for (int kj = 0; kj < 64; kj++) {
                float v[4];
                *(float4*)v = *(const float4*)&Vs[kj * SROW + tx * 4];
                float p0 = Ss[(ty * 4 + 0) * SROW + kj];
                float p1 = Ss[(ty * 4 + 1) * SROW + kj];
                float p2 = Ss[(ty * 4 + 2) * SROW + kj];
                float p3 = Ss[(ty * 4 + 3) * SROW + kj];
#pragma unroll
                for (int dd = 0; dd < 4; dd++) {
                    o[0][dd] += p0 * v[dd];
                    o[1][dd] += p1 * v[dd];
                    o[2][dd] += p2 * v[dd];
                    o[3][dd] += p3 * v[dd];
                }
            }
        }
    }

    // Final normalize + store: y[b, t, h*64 + d]
#pragma unroll
    for (int qq = 0; qq < 4; qq++) {
        const int qi = ty * 4 + qq;
        const float inv = 1.f / l_s[qi];
        float* yp = yatt + ((long)(b * T_ + q0 + qi) * C_) + h * D_ + tx * 4;
        *(float4*)yp = make_float4(o[qq][0] * inv, o[qq][1] * inv,
                                   o[qq][2] * inv, o[qq][3] * inv);
    }
}

// ---------------------------------------------------------------------------
extern "C" void kernel_launch(void* const* d_in, const int* in_sizes, int n_in,
                              void* d_out, int out_size) {
    const float* x     = (const float*)d_in[0];  // [B,T,C]
    const float* Wqkv  = (const float*)d_in[1];  // [3C, C]
    const float* Wproj = (const float*)d_in[2];  // [C, C]
    float* out = (float*)d_out;                  // [B,T,C]

    float* qkv = nullptr;
    float* att = nullptr;
    cudaGetSymbolAddress((void**)&qkv, g_qkv);
    cudaGetSymbolAddress((void**)&att, g_att);

    const int M = B_ * T_;  // 8192

    // 1) qkv = x @ Wqkv^T   [8192, 3072]
    {
        dim3 grid(3 * C_ / 128, M / 128);
        sgemm_nt<<<grid, 256>>>(x, Wqkv, qkv, M, 3 * C_, C_);
    }

    // 2) windowed attention -> att [8192, 1024]
    {
        const int smem = (4 * 64 * SROW + 3 * 64) * sizeof(float);  // ~70.2 KB
        cudaFuncSetAttribute(attn_kernel, cudaFuncAttributeMaxDynamicSharedMemorySize, smem);
        dim3 grid(T_ / 64, H_, B_);
        attn_kernel<<<grid, 256, smem>>>(qkv, att);
    }

    // 3) out = att @ Wproj^T  [8192, 1024]
    {
        dim3 grid(C_ / 128, M / 128);
        sgemm_nt<<<grid, 256>>>(att, Wproj, out, M, C_, C_);
    }
}

// round 7
// speedup vs baseline: 1.8693x; 1.8693x over previous
#include <cuda_runtime.h>
#include <cuda_bf16.h>
#include <cstdint>
#include <math.h>

#define B_ 4
#define T_ 2048
#define C_ 1024
#define H_ 16
#define D_ 64
#define WIN_ 256

#define GK 1024            // K of both GEMMs
#define CHUNK 32           // K elements per SMEM stage
#define NCHUNK (GK / CHUNK)

#define PW 20              // smem pitch in 32-bit words per row (16 data + 4 pad)
#define TILE_W (128 * PW)  // words per 128x32 bf16 tile
#define BUF_W (4 * TILE_W) // Ahi, Alo, Bhi, Blo
#define GEMM_SMEM (2 * BUF_W * 4)

// Scratch (allocation-free rule: __device__ globals)
__device__ float g_qkv[(size_t)B_ * T_ * 3 * C_];   // [B*T, 3C]
__device__ float g_att[(size_t)B_ * T_ * C_];       // [B*T, C]
__device__ __nv_bfloat16 g_xhi[(size_t)B_ * T_ * C_];
__device__ __nv_bfloat16 g_xlo[(size_t)B_ * T_ * C_];
__device__ __nv_bfloat16 g_ahi[(size_t)B_ * T_ * C_];
__device__ __nv_bfloat16 g_alo[(size_t)B_ * T_ * C_];
__device__ __nv_bfloat16 g_w1hi[(size_t)3 * C_ * C_];
__device__ __nv_bfloat16 g_w1lo[(size_t)3 * C_ * C_];
__device__ __nv_bfloat16 g_w2hi[(size_t)C_ * C_];
__device__ __nv_bfloat16 g_w2lo[(size_t)C_ * C_];

// ---------------------------------------------------------------------------
// helpers
// ---------------------------------------------------------------------------
__device__ __forceinline__ uint32_t smem_u32(const void* p) {
    uint32_t a;
    asm("{ .reg .u64 t; cvta.to.shared.u64 t, %1; cvt.u32.u64 %0, t; }" : "=r"(a) : "l"(p));
    return a;
}
__device__ __forceinline__ void cp16(uint32_t dst, const void* src) {
    asm volatile("cp.async.ca.shared.global [%0], [%1], 16;" :: "r"(dst), "l"(src));
}
__device__ __forceinline__ void mma_bf16(float* c, const uint32_t* a, const uint32_t* b) {
    asm volatile(
        "mma.sync.aligned.m16n8k16.row.col.f32.bf16.bf16.f32 "
        "{%0,%1,%2,%3}, {%4,%5,%6,%7}, {%8,%9}, {%0,%1,%2,%3};"
        : "+f"(c[0]), "+f"(c[1]), "+f"(c[2]), "+f"(c[3])
        : "r"(a[0]), "r"(a[1]), "r"(a[2]), "r"(a[3]), "r"(b[0]), "r"(b[1]));
}

// ---------------------------------------------------------------------------
// fp32 -> (hi, lo) bf16 split, rn rounding both: hi = bf16(f), lo = bf16(f - hi)
// ---------------------------------------------------------------------------
__global__ __launch_bounds__(256) void split_bf16(const float* __restrict__ in,
                                                  __nv_bfloat16* __restrict__ hi,
                                                  __nv_bfloat16* __restrict__ lo,
                                                  int n4) {
    int i = blockIdx.x * blockDim.x + threadIdx.x;
    if (i >= n4) return;
    float4 v = ((const float4*)in)[i];
    __nv_bfloat16 h0 = __float2bfloat16_rn(v.x);
    __nv_bfloat16 h1 = __float2bfloat16_rn(v.y);
    __nv_bfloat16 h2 = __float2bfloat16_rn(v.z);
    __nv_bfloat16 h3 = __float2bfloat16_rn(v.w);
    __nv_bfloat16 l0 = __float2bfloat16_rn(v.x - __bfloat162float(h0));
    __nv_bfloat16 l1 = __float2bfloat16_rn(v.y - __bfloat162float(h1));
    __nv_bfloat16 l2 = __float2bfloat16_rn(v.z - __bfloat162float(h2));
    __nv_bfloat16 l3 = __float2bfloat16_rn(v.w - __bfloat162float(h3));
    __nv_bfloat162* hp = (__nv_bfloat162*)hi;
    __nv_bfloat162* lp = (__nv_bfloat162*)lo;
    hp[2 * i] = __halves2bfloat162(h0, h1);
    hp[2 * i + 1] = __halves2bfloat162(h2, h3);
    lp[2 * i] = __halves2bfloat162(l0, l1);
    lp[2 * i + 1] = __halves2bfloat162(l2, l3);
}

// ---------------------------------------------------------------------------
// 3-term split-bf16 GEMM (NT): C[m,n] = sum_k A[m,k] * B[n,k], fp32 accum.
// CTA 128x128, 8 warps (2M x 4N), warp tile 64x32. K chunks of 32,
// cp.async double-buffered hi/lo tiles for A and B.
// ---------------------------------------------------------------------------
__global__ __launch_bounds__(256, 2) void gemm_split(const __nv_bfloat16* __restrict__ Ahi,
                                                     const __nv_bfloat16* __restrict__ Alo,
                                                     const __nv_bfloat16* __restrict__ Bhi,
                                                     const __nv_bfloat16* __restrict__ Blo,
                                                     float* __restrict__ Cm, int N) {
    extern __shared__ __align__(1024) uint32_t sw[];
    const int tid = threadIdx.x;
    const int wid = tid >> 5, lane = tid & 31;
    const int warp_m = wid >> 2, warp_n = wid & 3;
    const int gr = lane >> 2, lk = lane & 3;
    const int m0 = blockIdx.y * 128, n0 = blockIdx.x * 128;

    // producers: thread covers row (tid>>1), k-half (tid&1)*16 elements
    const int ldrow = tid >> 1, half = tid & 1;
    const long gofs = (long)ldrow * GK + half * 16;
    const __nv_bfloat16* srcs[4] = {Ahi + (long)m0 * GK + gofs, Alo + (long)m0 * GK + gofs,
                                    Bhi + (long)n0 * GK + gofs, Blo + (long)n0 * GK + gofs};
    const uint32_t sbase = smem_u32(sw);
    const uint32_t drow = (uint32_t)ldrow * (PW * 4) + (uint32_t)half * 32;

    float acc[4][4][4];
#pragma unroll
    for (int mt = 0; mt < 4; mt++)
#pragma unroll
        for (int nt = 0; nt < 4; nt++)
#pragma unroll
            for (int i = 0; i < 4; i++) acc[mt][nt][i] = 0.f;

    // prologue: stage chunk 0 into buffer 0
#pragma unroll
    for (int t = 0; t < 4; t++) {
        const uint32_t d = sbase + (uint32_t)t * (TILE_W * 4) + drow;
        cp16(d, srcs[t]);
        cp16(d + 16, srcs[t] + 8);
    }
    asm volatile("cp.async.commit_group;" ::: "memory");

    for (int c = 0; c < NCHUNK; ++c) {
        if (c + 1 < NCHUNK) {
            const uint32_t boff = (uint32_t)((c + 1) & 1) * (BUF_W * 4);
#pragma unroll
            for (int t = 0; t < 4; t++) {
                const uint32_t d = sbase + boff + (uint32_t)t * (TILE_W * 4) + drow;
                const __nv_bfloat16* s = srcs[t] + (c + 1) * CHUNK;
                cp16(d, s);
                cp16(d + 16, s + 8);
            }
            asm volatile("cp.async.commit_group;" ::: "memory");
            asm volatile("cp.async.wait_group 1;" ::: "memory");
        } else {
            asm volatile("cp.async.wait_group 0;" ::: "memory");
        }
        __syncthreads();

        const uint32_t* Ash = sw + (c & 1) * BUF_W;
        const uint32_t* Asl = Ash + TILE_W;
        const uint32_t* Bsh = Ash + 2 * TILE_W;
        const uint32_t* Bsl = Ash + 3 * TILE_W;
#pragma unroll
        for (int s = 0; s < 2; s++) {   // two k16 steps per 32-chunk
            const int kw = s * 8 + lk;  // word index of pair (2lk) within row
            uint32_t ah[4][4], bh[4][2], bl[4][2], al[4][4];
#pragma unroll
            for (int mt = 0; mt < 4; mt++) {
                const int r = (warp_m * 64 + mt * 16 + gr) * PW;
                ah[mt][0] = Ash[r + kw];
                ah[mt][1] = Ash[r + 8 * PW + kw];
                ah[mt][2] = Ash[r + kw + 4];
                ah[mt][3] = Ash[r + 8 * PW + kw + 4];
            }
#pragma unroll
            for (int nt = 0; nt < 4; nt++) {
                const int r = (warp_n * 32 + nt * 8 + gr) * PW;
                bh[nt][0] = Bsh[r + kw];
                bh[nt][1] = Bsh[r + kw + 4];
            }
#pragma unroll
            for (int mt = 0; mt < 4; mt++)
#pragma unroll
                for (int nt = 0; nt < 4; nt++)
                    mma_bf16(acc[mt][nt], ah[mt], bh[nt]);   // hi*hi
#pragma unroll
            for (int nt = 0; nt < 4; nt++) {
                const int r = (warp_n * 32 + nt * 8 + gr) * PW;
                bl[nt][0] = Bsl[r + kw];
                bl[nt][1] = Bsl[r + kw + 4];
            }
#pragma unroll
            for (int mt = 0; mt < 4; mt++)
#pragma unroll
                for (int nt = 0; nt < 4; nt++)
                    mma_bf16(acc[mt][nt], ah[mt], bl[nt]);   // hi*lo
#pragma unroll
            for (int mt = 0; mt < 4; mt++) {
                const int r = (warp_m * 64 + mt * 16 + gr) * PW;
                al[mt][0] = Asl[r + kw];
                al[mt][1] = Asl[r + 8 * PW + kw];
                al[mt][2] = Asl[r + kw + 4];
                al[mt][3] = Asl[r + 8 * PW + kw + 4];
            }
#pragma unroll
            for (int mt = 0; mt < 4; mt++)
#pragma unroll
                for (int nt = 0; nt < 4; nt++)
                    mma_bf16(acc[mt][nt], al[mt], bh[nt]);   // lo*hi
        }
        __syncthreads();
    }

    // epilogue: c0,c1 at (gr, 2lk), c2,c3 at (gr+8, 2lk)
#pragma unroll
    for (int mt = 0; mt < 4; mt++) {
        const int m = m0 + warp_m * 64 + mt * 16 + gr;
#pragma unroll
        for (int nt = 0; nt < 4; nt++) {
            const int n = n0 + warp_n * 32 + nt * 8 + 2 * lk;
            *(float2*)&Cm[(long)m * N + n] = make_float2(acc[mt][nt][0], acc[mt][nt][1]);
            *(float2*)&Cm[(long)(m + 8) * N + n] = make_float2(acc[mt][nt][2], acc[mt][nt][3]);
        }
    }
}

// ---------------------------------------------------------------------------
// Sliding-window attention (unchanged from passing R2 kernel)
// ---------------------------------------------------------------------------
#define SROW 68
__global__ __launch_bounds__(256) void attn_kernel(const float* __restrict__ qkv,
                                                   float* __restrict__ yatt) {
    extern __shared__ __align__(1024) unsigned char dynsmem[];
    float* sm = (float*)dynsmem;
    float* Qs = sm;
    float* Ks = Qs + 64 * SROW;
    float* Vs = Ks + 64 * SROW;
    float* Ss = Vs + 64 * SROW;
    float* m_s = Ss + 64 * SROW;
    float* l_s = m_s + 64;
    float* corr_s = l_s + 64;

    const int qt = blockIdx.x, h = blockIdx.y, b = blockIdx.z;
    const int q0 = qt * 64;
    const int tid = threadIdx.x;
    const int tx = tid & 15, ty = tid >> 4;
    const float scale = 0.125f;

    {
        const int qi = tid >> 2, part = tid & 3;
        const float* qp = qkv + ((long)(b * T_ + q0 + qi) * (3 * C_)) + h * D_ + part * 16;
#pragma unroll
        for (int i = 0; i < 16; i += 4) {
            float4 v = *(const float4*)(qp + i);
            Qs[(part * 16 + i + 0) * SROW + qi] = v.x * scale;
            Qs[(part * 16 + i + 1) * SROW + qi] = v.y * scale;
            Qs[(part * 16 + i + 2) * SROW + qi] = v.z * scale;
            Qs[(part * 16 + i + 3) * SROW + qi] = v.w * scale;
        }
        if (tid < 64) { m_s[tid] = -1e30f; l_s[tid] = 0.f; }
    }

    float o[4][4];
#pragma unroll
    for (int i = 0; i < 4; i++)
#pragma unroll
        for (int j = 0; j < 4; j++) o[i][j] = 0.f;

    const int kt0 = (qt >= 4) ? (qt - 4) : 0;
    for (int kt = kt0; kt <= qt; kt++) {
        __syncthreads();
        {
            const int kj = tid >> 2, part = tid & 3;
            const float* kp = qkv + ((long)(b * T_ + kt * 64 + kj) * (3 * C_)) + C_ + h * D_ + part * 16;
            const float* vp = kp + C_;
#pragma unroll
            for (int i = 0; i < 16; i += 4) {
                float4 kv = *(const float4*)(kp + i);
                Ks[(part * 16 + i + 0) * SROW + kj] = kv.x;
                Ks[(part * 16 + i + 1) * SROW + kj] = kv.y;
                Ks[(part * 16 + i + 2) * SROW + kj] = kv.z;
                Ks[(part * 16 + i + 3) * SROW + kj] = kv.w;
                float4 vv = *(const float4*)(vp + i);
                *(float4*)&Vs[kj * SROW + part * 16 + i] = vv;
            }
        }
        __syncthreads();

        {
            float s[4][4];
#pragma unroll
            for (int i = 0; i < 4; i++)
#pragma unroll
                for (int j = 0; j < 4; j++) s[i][j] = 0.f;
#pragma unroll
            for (int d = 0; d < 64; d++) {
                float a[4], cc[4];
                *(float4*)a = *(const float4*)&Qs[d * SROW + ty * 4];
                *(float4*)cc = *(const float4*)&Ks[d * SROW + tx * 4];
#pragma unroll
                for (int qq = 0; qq < 4; qq++)
#pragma unroll
                    for (int kk = 0; kk < 4; kk++)
                        s[qq][kk] += a[qq] * cc[kk];
            }
#pragma unroll
            for (int qq = 0; qq < 4; qq++) {
                const int qg = q0 + ty * 4 + qq;
                float4 rowv;
                float* rp = &rowv.x;
#pragma unroll
                for (int kk = 0; kk < 4; kk++) {
                    const int jg = kt * 64 + tx * 4 + kk;
                    const bool valid = (jg <= qg) && (jg > qg - WIN_);
                    rp[kk] = valid ? s[qq][kk] : -1e30f;
                }
                *(float4*)&Ss[(ty * 4 + qq) * SROW + tx * 4] = rowv;
            }
        }
        __syncthreads();

        {
            const int qi = tid >> 2, part = tid & 3;
            float* srow = &Ss[qi * SROW + part * 16];
            float mx = -1e30f;
#pragma unroll
            for (int j = 0; j < 16; j++) mx = fmaxf(mx, srow[j]);
            mx = fmaxf(mx, __shfl_xor_sync(0xffffffffu, mx, 1));
            mx = fmaxf(mx, __shfl_xor_sync(0xffffffffu, mx, 2));
            const float m_old = m_s[qi];
            const float m_new = fmaxf(m_old, mx);
            float lsum = 0.f;
#pragma unroll
            for (int j = 0; j < 16; j++) {
                float p = __expf(srow[j] - m_new);
                srow[j] = p;
                lsum += p;
            }
            lsum += __shfl_xor_sync(0xffffffffu, lsum, 1);
            lsum += __shfl_xor_sync(0xffffffffu, lsum, 2);
            if (part == 0) {
                const float corr = __expf(m_old - m_new);
                corr_s[qi] = corr;
                l_s[qi] = l_s[qi] * corr + lsum;
                m_s[qi] = m_new;
            }
        }
        __syncthreads();

        {
            float cc[4];
#pragma unroll
            for (int qq = 0; qq < 4; qq++) cc[qq] = corr_s[ty * 4 + qq];
#pragma unroll
            for (int qq = 0; qq < 4; qq++)
#pragma unroll
                for (int dd = 0; dd < 4; dd++) o[qq][dd] *= cc[qq];
#pragma unroll
            for (int kj = 0; kj < 64; kj++) {
                float v[4];
                *(float4*)v = *(const float4*)&Vs[kj * SROW + tx * 4];
                float p0 = Ss[(ty * 4 + 0) * SROW + kj];
                float p1 = Ss[(ty * 4 + 1) * SROW + kj];
                float p2 = Ss[(ty * 4 + 2) * SROW + kj];
                float p3 = Ss[(ty * 4 + 3) * SROW + kj];
#pragma unroll
                for (int dd = 0; dd < 4; dd++) {
                    o[0][dd] += p0 * v[dd];
                    o[1][dd] += p1 * v[dd];
                    o[2][dd] += p2 * v[dd];
                    o[3][dd] += p3 * v[dd];
                }
            }
        }
    }

#pragma unroll
    for (int qq = 0; qq < 4; qq++) {
        const int qi = ty * 4 + qq;
        const float inv = 1.f / l_s[qi];
        float* yp = yatt + ((long)(b * T_ + q0 + qi) * C_) + h * D_ + tx * 4;
        *(float4*)yp = make_float4(o[qq][0] * inv, o[qq][1] * inv,
                                   o[qq][2] * inv, o[qq][3] * inv);
    }
}

// ---------------------------------------------------------------------------
extern "C" void kernel_launch(void* const* d_in, const int* in_sizes, int n_in,
                              void* d_out, int out_size) {
    const float* x     = (const float*)d_in[0];  // [B,T,C]
    const float* Wqkv  = (const float*)d_in[1];  // [3C, C]
    const float* Wproj = (const float*)d_in[2];  // [C, C]
    float* out = (float*)d_out;                  // [B,T,C]

    float *qkv, *att;
    __nv_bfloat16 *xhi, *xlo, *ahi, *alo, *w1hi, *w1lo, *w2hi, *w2lo;
    cudaGetSymbolAddress((void**)&qkv, g_qkv);
    cudaGetSymbolAddress((void**)&att, g_att);
    cudaGetSymbolAddress((void**)&xhi, g_xhi);
    cudaGetSymbolAddress((void**)&xlo, g_xlo);
    cudaGetSymbolAddress((void**)&ahi, g_ahi);
    cudaGetSymbolAddress((void**)&alo, g_alo);
    cudaGetSymbolAddress((void**)&w1hi, g_w1hi);
    cudaGetSymbolAddress((void**)&w1lo, g_w1lo);
    cudaGetSymbolAddress((void**)&w2hi, g_w2hi);
    cudaGetSymbolAddress((void**)&w2lo, g_w2lo);

    const int M = B_ * T_;  // 8192
    cudaFuncSetAttribute(gemm_split, cudaFuncAttributeMaxDynamicSharedMemorySize, GEMM_SMEM);

    // 0) split inputs into bf16 hi/lo planes
    {
        int nx = M * C_ / 4;
        split_bf16<<<(nx + 255) / 256, 256>>>(x, xhi, xlo, nx);
        int nw1 = 3 * C_ * C_ / 4;
        split_bf16<<<(nw1 + 255) / 256, 256>>>(Wqkv, w1hi, w1lo, nw1);
        int nw2 = C_ * C_ / 4;
        split_bf16<<<(nw2 + 255) / 256, 256>>>(Wproj, w2hi, w2lo, nw2);
    }

    // 1) qkv = x @ Wqkv^T   [8192, 3072]
    {
        dim3 grid(3 * C_ / 128, M / 128);
        gemm_split<<<grid, 256, GEMM_SMEM>>>(xhi, xlo, w1hi, w1lo, qkv, 3 * C_);
    }

    // 2) windowed attention -> att [8192, 1024]
    {
        const int smem = (4 * 64 * SROW + 3 * 64) * sizeof(float);
        cudaFuncSetAttribute(attn_kernel, cudaFuncAttributeMaxDynamicSharedMemorySize, smem);
        dim3 grid(T_ / 64, H_, B_);
        attn_kernel<<<grid, 256, smem>>>(qkv, att);
    }

    // 2b) split attention output
    {
        int na = M * C_ / 4;
        split_bf16<<<(na + 255) / 256, 256>>>(att, ahi, alo, na);
    }

    // 3) out = att @ Wproj^T  [8192, 1024]
    {
        dim3 grid(C_ / 128, M / 128);
        gemm_split<<<grid, 256, GEMM_SMEM>>>(ahi, alo, w2hi, w2lo, out, C_);
    }
}

// round 11
// speedup vs baseline: 2.1798x; 1.1661x over previous
#include <cuda_runtime.h>
#include <cuda_bf16.h>
#include <cstdint>
#include <math.h>

#define B_ 4
#define T_ 2048
#define C_ 1024
#define H_ 16
#define D_ 64
#define WIN_ 256

#define GK 1024            // K of both GEMMs
#define CHUNK 32           // K elements per SMEM stage
#define NCHUNK (GK / CHUNK)

#define PW 20              // smem pitch in 32-bit words per row (16 data + 4 pad)
#define TILE_W (128 * PW)  // words per 128x32 bf16 tile
#define BUF_W (4 * TILE_W) // Ahi, Alo, Bhi, Blo
#define GEMM_SMEM (2 * BUF_W * 4)

// Scratch (allocation-free rule: __device__ globals)
__device__ float g_qkv[(size_t)B_ * T_ * 3 * C_];   // [B*T, 3C]
__device__ float g_att[(size_t)B_ * T_ * C_];       // [B*T, C]
__device__ __nv_bfloat16 g_xhi[(size_t)B_ * T_ * C_];
__device__ __nv_bfloat16 g_xlo[(size_t)B_ * T_ * C_];
__device__ __nv_bfloat16 g_ahi[(size_t)B_ * T_ * C_];
__device__ __nv_bfloat16 g_alo[(size_t)B_ * T_ * C_];
__device__ __nv_bfloat16 g_w1hi[(size_t)3 * C_ * C_];
__device__ __nv_bfloat16 g_w1lo[(size_t)3 * C_ * C_];
__device__ __nv_bfloat16 g_w2hi[(size_t)C_ * C_];
__device__ __nv_bfloat16 g_w2lo[(size_t)C_ * C_];

// ---------------------------------------------------------------------------
// helpers
// ---------------------------------------------------------------------------
__device__ __forceinline__ uint32_t smem_u32(const void* p) {
    uint32_t a;
    asm("{ .reg .u64 t; cvta.to.shared.u64 t, %1; cvt.u32.u64 %0, t; }" : "=r"(a) : "l"(p));
    return a;
}
__device__ __forceinline__ void cp16(uint32_t dst, const void* src) {
    asm volatile("cp.async.ca.shared.global [%0], [%1], 16;" :: "r"(dst), "l"(src));
}
__device__ __forceinline__ void mma_bf16(float* c, const uint32_t* a, const uint32_t* b) {
    asm volatile(
        "mma.sync.aligned.m16n8k16.row.col.f32.bf16.bf16.f32 "
        "{%0,%1,%2,%3}, {%4,%5,%6,%7}, {%8,%9}, {%0,%1,%2,%3};"
        : "+f"(c[0]), "+f"(c[1]), "+f"(c[2]), "+f"(c[3])
        : "r"(a[0]), "r"(a[1]), "r"(a[2]), "r"(a[3]), "r"(b[0]), "r"(b[1]));
}
__device__ __forceinline__ void ldsm4(uint32_t* r, uint32_t addr) {
    asm volatile("ldmatrix.sync.aligned.m8n8.x4.shared.b16 {%0,%1,%2,%3}, [%4];"
                 : "=r"(r[0]), "=r"(r[1]), "=r"(r[2]), "=r"(r[3]) : "r"(addr));
}

// ---------------------------------------------------------------------------
// fp32 -> (hi, lo) bf16 split, rn rounding both: hi = bf16(f), lo = bf16(f - hi)
// ---------------------------------------------------------------------------
__global__ __launch_bounds__(256) void split_bf16(const float* __restrict__ in,
                                                  __nv_bfloat16* __restrict__ hi,
                                                  __nv_bfloat16* __restrict__ lo,
                                                  int n4) {
    int i = blockIdx.x * blockDim.x + threadIdx.x;
    if (i >= n4) return;
    float4 v = ((const float4*)in)[i];
    __nv_bfloat16 h0 = __float2bfloat16_rn(v.x);
    __nv_bfloat16 h1 = __float2bfloat16_rn(v.y);
    __nv_bfloat16 h2 = __float2bfloat16_rn(v.z);
    __nv_bfloat16 h3 = __float2bfloat16_rn(v.w);
    __nv_bfloat16 l0 = __float2bfloat16_rn(v.x - __bfloat162float(h0));
    __nv_bfloat16 l1 = __float2bfloat16_rn(v.y - __bfloat162float(h1));
    __nv_bfloat16 l2 = __float2bfloat16_rn(v.z - __bfloat162float(h2));
    __nv_bfloat16 l3 = __float2bfloat16_rn(v.w - __bfloat162float(h3));
    __nv_bfloat162* hp = (__nv_bfloat162*)hi;
    __nv_bfloat162* lp = (__nv_bfloat162*)lo;
    hp[2 * i] = __halves2bfloat162(h0, h1);
    hp[2 * i + 1] = __halves2bfloat162(h2, h3);
    lp[2 * i] = __halves2bfloat162(l0, l1);
    lp[2 * i + 1] = __halves2bfloat162(l2, l3);
}

// ---------------------------------------------------------------------------
// 3-term split-bf16 GEMM (NT): C[m,n] = sum_k A[m,k] * B[n,k], fp32 accum.
// CTA 128x128, 8 warps (2M x 4N), warp tile 64x32. K chunks of 32,
// cp.async double-buffered hi/lo tiles; ldmatrix fragment feeds.
// ---------------------------------------------------------------------------
__global__ __launch_bounds__(256, 2) void gemm_split(const __nv_bfloat16* __restrict__ Ahi,
                                                     const __nv_bfloat16* __restrict__ Alo,
                                                     const __nv_bfloat16* __restrict__ Bhi,
                                                     const __nv_bfloat16* __restrict__ Blo,
                                                     float* __restrict__ Cm, int N) {
    extern __shared__ __align__(1024) uint32_t sw[];
    const int tid = threadIdx.x;
    const int wid = tid >> 5, lane = tid & 31;
    const int warp_m = wid >> 2, warp_n = wid & 3;
    const int gr = lane >> 2, lk = lane & 3;
    const int m0 = blockIdx.y * 128, n0 = blockIdx.x * 128;

    // producers: thread covers row (tid>>1), k-half (tid&1)*16 elements
    const int ldrow = tid >> 1, half = tid & 1;
    const long gofs = (long)ldrow * GK + half * 16;
    const __nv_bfloat16* srcs[4] = {Ahi + (long)m0 * GK + gofs, Alo + (long)m0 * GK + gofs,
                                    Bhi + (long)n0 * GK + gofs, Blo + (long)n0 * GK + gofs};
    const uint32_t sbase = smem_u32(sw);
    const uint32_t drow = (uint32_t)ldrow * (PW * 4) + (uint32_t)half * 32;

    // ldmatrix per-lane base offsets (bytes), within a tile
    // A x4: lanes 0-7 -> rows 0-7 k0, 8-15 -> rows 8-15 k0, 16-23 -> rows 0-7 k+8, 24-31 -> rows 8-15 k+8
    const uint32_t aoff = (uint32_t)(warp_m * 64 + (lane & 15)) * (PW * 4) + ((uint32_t)(lane >> 4) << 4);
    // B x4 (covers nt pair): lanes 0-7 -> n rows 0-7 k0, 8-15 -> rows 0-7 k+8,
    //                        16-23 -> rows 8-15 k0, 24-31 -> rows 8-15 k+8
    const uint32_t boff = (uint32_t)(warp_n * 32 + ((lane >> 4) & 1) * 8 + (lane & 7)) * (PW * 4)
                          + (((uint32_t)(lane >> 3) & 1) << 4);

    float acc[4][4][4];
#pragma unroll
    for (int mt = 0; mt < 4; mt++)
#pragma unroll
        for (int nt = 0; nt < 4; nt++)
#pragma unroll
            for (int i = 0; i < 4; i++) acc[mt][nt][i] = 0.f;

    // prologue: stage chunk 0 into buffer 0
#pragma unroll
    for (int t = 0; t < 4; t++) {
        const uint32_t d = sbase + (uint32_t)t * (TILE_W * 4) + drow;
        cp16(d, srcs[t]);
        cp16(d + 16, srcs[t] + 8);
    }
    asm volatile("cp.async.commit_group;" ::: "memory");

    for (int c = 0; c < NCHUNK; ++c) {
        if (c + 1 < NCHUNK) {
            const uint32_t bo = (uint32_t)((c + 1) & 1) * (BUF_W * 4);
#pragma unroll
            for (int t = 0; t < 4; t++) {
                const uint32_t d = sbase + bo + (uint32_t)t * (TILE_W * 4) + drow;
                const __nv_bfloat16* s = srcs[t] + (c + 1) * CHUNK;
                cp16(d, s);
                cp16(d + 16, s + 8);
            }
            asm volatile("cp.async.commit_group;" ::: "memory");
            asm volatile("cp.async.wait_group 1;" ::: "memory");
        } else {
            asm volatile("cp.async.wait_group 0;" ::: "memory");
        }
        __syncthreads();

        const uint32_t bufb = sbase + (uint32_t)(c & 1) * (BUF_W * 4);
        const uint32_t ah_b = bufb + aoff;                       // Ahi tile
        const uint32_t al_b = bufb + TILE_W * 4 + aoff;          // Alo tile
        const uint32_t bh_b = bufb + 2 * TILE_W * 4 + boff;      // Bhi tile
        const uint32_t bl_b = bufb + 3 * TILE_W * 4 + boff;      // Blo tile
#pragma unroll
        for (int s = 0; s < 2; s++) {   // two k16 steps per 32-chunk
            const uint32_t ks = (uint32_t)s * 32u;  // 8 words
            uint32_t ah[4][4], al[4][4], bh[2][4], bl[2][4];
#pragma unroll
            for (int mt = 0; mt < 4; mt++) ldsm4(ah[mt], ah_b + (uint32_t)mt * (16 * PW * 4) + ks);
#pragma unroll
            for (int p = 0; p < 2; p++) ldsm4(bh[p], bh_b + (uint32_t)p * (16 * PW * 4) + ks);
#pragma unroll
            for (int mt = 0; mt < 4; mt++)
#pragma unroll
                for (int nt = 0; nt < 4; nt++)
                    mma_bf16(acc[mt][nt], ah[mt], &bh[nt >> 1][(nt & 1) * 2]);   // hi*hi
#pragma unroll
            for (int p = 0; p < 2; p++) ldsm4(bl[p], bl_b + (uint32_t)p * (16 * PW * 4) + ks);
#pragma unroll
            for (int mt = 0; mt < 4; mt++)
#pragma unroll
                for (int nt = 0; nt < 4; nt++)
                    mma_bf16(acc[mt][nt], ah[mt], &bl[nt >> 1][(nt & 1) * 2]);   // hi*lo
#pragma unroll
            for (int mt = 0; mt < 4; mt++) ldsm4(al[mt], al_b + (uint32_t)mt * (16 * PW * 4) + ks);
#pragma unroll
            for (int mt = 0; mt < 4; mt++)
#pragma unroll
                for (int nt = 0; nt < 4; nt++)
                    mma_bf16(acc[mt][nt], al[mt], &bh[nt >> 1][(nt & 1) * 2]);   // lo*hi
        }
        __syncthreads();
    }

    // epilogue: c0,c1 at (gr, 2lk), c2,c3 at (gr+8, 2lk)
#pragma unroll
    for (int mt = 0; mt < 4; mt++) {
        const int m = m0 + warp_m * 64 + mt * 16 + gr;
#pragma unroll
        for (int nt = 0; nt < 4; nt++) {
            const int n = n0 + warp_n * 32 + nt * 8 + 2 * lk;
            *(float2*)&Cm[(long)m * N + n] = make_float2(acc[mt][nt][0], acc[mt][nt][1]);
            *(float2*)&Cm[(long)(m + 8) * N + n] = make_float2(acc[mt][nt][2], acc[mt][nt][3]);
        }
    }
}

// ---------------------------------------------------------------------------
// Sliding-window attention (unchanged from passing R2 kernel)
// ---------------------------------------------------------------------------
#define SROW 68
__global__ __launch_bounds__(256) void attn_kernel(const float* __restrict__ qkv,
                                                   float* __restrict__ yatt) {
    extern __shared__ __align__(1024) unsigned char dynsmem[];
    float* sm = (float*)dynsmem;
    float* Qs = sm;
    float* Ks = Qs + 64 * SROW;
    float* Vs = Ks + 64 * SROW;
    float* Ss = Vs + 64 * SROW;
    float* m_s = Ss + 64 * SROW;
    float* l_s = m_s + 64;
    float* corr_s = l_s + 64;

    const int qt = blockIdx.x, h = blockIdx.y, b = blockIdx.z;
    const int q0 = qt * 64;
    const int tid = threadIdx.x;
    const int tx = tid & 15, ty = tid >> 4;
    const float scale = 0.125f;

    {
        const int qi = tid >> 2, part = tid & 3;
        const float* qp = qkv + ((long)(b * T_ + q0 + qi) * (3 * C_)) + h * D_ + part * 16;
#pragma unroll
        for (int i = 0; i < 16; i += 4) {
            float4 v = *(const float4*)(qp + i);
            Qs[(part * 16 + i + 0) * SROW + qi] = v.x * scale;
            Qs[(part * 16 + i + 1) * SROW + qi] = v.y * scale;
            Qs[(part * 16 + i + 2) * SROW + qi] = v.z * scale;
            Qs[(part * 16 + i + 3) * SROW + qi] = v.w * scale;
        }
        if (tid < 64) { m_s[tid] = -1e30f; l_s[tid] = 0.f; }
    }

    float o[4][4];
#pragma unroll
    for (int i = 0; i < 4; i++)
#pragma unroll
        for (int j = 0; j < 4; j++) o[i][j] = 0.f;

    const int kt0 = (qt >= 4) ? (qt - 4) : 0;
    for (int kt = kt0; kt <= qt; kt++) {
        __syncthreads();
        {
            const int kj = tid >> 2, part = tid & 3;
            const float* kp = qkv + ((long)(b * T_ + kt * 64 + kj) * (3 * C_)) + C_ + h * D_ + part * 16;
            const float* vp = kp + C_;
#pragma unroll
            for (int i = 0; i < 16; i += 4) {
                float4 kv = *(const float4*)(kp + i);
                Ks[(part * 16 + i + 0) * SROW + kj] = kv.x;
                Ks[(part * 16 + i + 1) * SROW + kj] = kv.y;
                Ks[(part * 16 + i + 2) * SROW + kj] = kv.z;
                Ks[(part * 16 + i + 3) * SROW + kj] = kv.w;
                float4 vv = *(const float4*)(vp + i);
                *(float4*)&Vs[kj * SROW + part * 16 + i] = vv;
            }
        }
        __syncthreads();

        {
            float s[4][4];
#pragma unroll
            for (int i = 0; i < 4; i++)
#pragma unroll
                for (int j = 0; j < 4; j++) s[i][j] = 0.f;
#pragma unroll
            for (int d = 0; d < 64; d++) {
                float a[4], cc[4];
                *(float4*)a = *(const float4*)&Qs[d * SROW + ty * 4];
                *(float4*)cc = *(const float4*)&Ks[d * SROW + tx * 4];
#pragma unroll
                for (int qq = 0; qq < 4; qq++)
#pragma unroll
                    for (int kk = 0; kk < 4; kk++)
                        s[qq][kk] += a[qq] * cc[kk];
            }
#pragma unroll
            for (int qq = 0; qq < 4; qq++) {
                const int qg = q0 + ty * 4 + qq;
                float4 rowv;
                float* rp = &rowv.x;
#pragma unroll
                for (int kk = 0; kk < 4; kk++) {
                    const int jg = kt * 64 + tx * 4 + kk;
                    const bool valid = (jg <= qg) && (jg > qg - WIN_);
                    rp[kk] = valid ? s[qq][kk] : -1e30f;
                }
                *(float4*)&Ss[(ty * 4 + qq) * SROW + tx * 4] = rowv;
            }
        }
        __syncthreads();

        {
            const int qi = tid >> 2, part = tid & 3;
            float* srow = &Ss[qi * SROW + part * 16];
            float mx = -1e30f;
#pragma unroll
            for (int j = 0; j < 16; j++) mx = fmaxf(mx, srow[j]);
            mx = fmaxf(mx, __shfl_xor_sync(0xffffffffu, mx, 1));
            mx = fmaxf(mx, __shfl_xor_sync(0xffffffffu, mx, 2));
            const float m_old = m_s[qi];
            const float m_new = fmaxf(m_old, mx);
            float lsum = 0.f;
#pragma unroll
            for (int j = 0; j < 16; j++) {
                float p = __expf(srow[j] - m_new);
                srow[j] = p;
                lsum += p;
            }
            lsum += __shfl_xor_sync(0xffffffffu, lsum, 1);
            lsum += __shfl_xor_sync(0xffffffffu, lsum, 2);
            if (part == 0) {
                const float corr = __expf(m_old - m_new);
                corr_s[qi] = corr;
                l_s[qi] = l_s[qi] * corr + lsum;
                m_s[qi] = m_new;
            }
        }
        __syncthreads();

        {
            float cc[4];
#pragma unroll
            for (int qq = 0; qq < 4; qq++) cc[qq] = corr_s[ty * 4 + qq];
#pragma unroll
            for (int qq = 0; qq < 4; qq++)
#pragma unroll
                for (int dd = 0; dd < 4; dd++) o[qq][dd] *= cc[qq];
#pragma unroll
            for (int kj = 0; kj < 64; kj++) {
                float v[4];
                *(float4*)v = *(const float4*)&Vs[kj * SROW + tx * 4];
                float p0 = Ss[(ty * 4 + 0) * SROW + kj];
                float p1 = Ss[(ty * 4 + 1) * SROW + kj];
                float p2 = Ss[(ty * 4 + 2) * SROW + kj];
                float p3 = Ss[(ty * 4 + 3) * SROW + kj];
#pragma unroll
                for (int dd = 0; dd < 4; dd++) {
                    o[0][dd] += p0 * v[dd];
                    o[1][dd] += p1 * v[dd];
                    o[2][dd] += p2 * v[dd];
                    o[3][dd] += p3 * v[dd];
                }
            }
        }
    }

#pragma unroll
    for (int qq = 0; qq < 4; qq++) {
        const int qi = ty * 4 + qq;
        const float inv = 1.f / l_s[qi];
        float* yp = yatt + ((long)(b * T_ + q0 + qi) * C_) + h * D_ + tx * 4;
        *(float4*)yp = make_float4(o[qq][0] * inv, o[qq][1] * inv,
                                   o[qq][2] * inv, o[qq][3] * inv);
    }
}

// ---------------------------------------------------------------------------
extern "C" void kernel_launch(void* const* d_in, const int* in_sizes, int n_in,
                              void* d_out, int out_size) {
    const float* x     = (const float*)d_in[0];  // [B,T,C]
    const float* Wqkv  = (const float*)d_in[1];  // [3C, C]
    const float* Wproj = (const float*)d_in[2];  // [C, C]
    float* out = (float*)d_out;                  // [B,T,C]

    float *qkv, *att;
    __nv_bfloat16 *xhi, *xlo, *ahi, *alo, *w1hi, *w1lo, *w2hi, *w2lo;
    cudaGetSymbolAddress((void**)&qkv, g_qkv);
    cudaGetSymbolAddress((void**)&att, g_att);
    cudaGetSymbolAddress((void**)&xhi, g_xhi);
    cudaGetSymbolAddress((void**)&xlo, g_xlo);
    cudaGetSymbolAddress((void**)&ahi, g_ahi);
    cudaGetSymbolAddress((void**)&alo, g_alo);
    cudaGetSymbolAddress((void**)&w1hi, g_w1hi);
    cudaGetSymbolAddress((void**)&w1lo, g_w1lo);
    cudaGetSymbolAddress((void**)&w2hi, g_w2hi);
    cudaGetSymbolAddress((void**)&w2lo, g_w2lo);

    const int M = B_ * T_;  // 8192
    cudaFuncSetAttribute(gemm_split, cudaFuncAttributeMaxDynamicSharedMemorySize, GEMM_SMEM);

    // 0) split inputs into bf16 hi/lo planes
    {
        int nx = M * C_ / 4;
        split_bf16<<<(nx + 255) / 256, 256>>>(x, xhi, xlo, nx);
        int nw1 = 3 * C_ * C_ / 4;
        split_bf16<<<(nw1 + 255) / 256, 256>>>(Wqkv, w1hi, w1lo, nw1);
        int nw2 = C_ * C_ / 4;
        split_bf16<<<(nw2 + 255) / 256, 256>>>(Wproj, w2hi, w2lo, nw2);
    }

    // 1) qkv = x @ Wqkv^T   [8192, 3072]
    {
        dim3 grid(3 * C_ / 128, M / 128);
        gemm_split<<<grid, 256, GEMM_SMEM>>>(xhi, xlo, w1hi, w1lo, qkv, 3 * C_);
    }

    // 2) windowed attention -> att [8192, 1024]
    {
        const int smem = (4 * 64 * SROW + 3 * 64) * sizeof(float);
        cudaFuncSetAttribute(attn_kernel, cudaFuncAttributeMaxDynamicSharedMemorySize, smem);
        dim3 grid(T_ / 64, H_, B_);
        attn_kernel<<<grid, 256, smem>>>(qkv, att);
    }

    // 2b) split attention output
    {
        int na = M * C_ / 4;
        split_bf16<<<(na + 255) / 256, 256>>>(att, ahi, alo, na);
    }

    // 3) out = att @ Wproj^T  [8192, 1024]
    {
        dim3 grid(C_ / 128, M / 128);
        gemm_split<<<grid, 256, GEMM_SMEM>>>(ahi, alo, w2hi, w2lo, out, C_);
    }
}

// round 12
// speedup vs baseline: 2.7911x; 1.2804x over previous
#include <cuda_runtime.h>
#include <cuda_bf16.h>
#include <cstdint>
#include <math.h>

#define B_ 4
#define T_ 2048
#define C_ 1024
#define H_ 16
#define D_ 64
#define WIN_ 256

#define GK 1024            // K of both GEMMs
#define CHUNK 32           // K elements per SMEM stage
#define NCHUNK (GK / CHUNK)

#define PW 20              // gemm smem pitch in 32-bit words per row
#define TILE_W (128 * PW)
#define BUF_W (4 * TILE_W)
#define GEMM_SMEM (2 * BUF_W * 4)

// Scratch (allocation-free rule: __device__ globals)
__device__ float g_qkv[(size_t)B_ * T_ * 3 * C_];   // [B*T, 3C]
__device__ float g_att[(size_t)B_ * T_ * C_];       // [B*T, C]
__device__ __nv_bfloat16 g_xhi[(size_t)B_ * T_ * C_];
__device__ __nv_bfloat16 g_xlo[(size_t)B_ * T_ * C_];
__device__ __nv_bfloat16 g_ahi[(size_t)B_ * T_ * C_];
__device__ __nv_bfloat16 g_alo[(size_t)B_ * T_ * C_];
__device__ __nv_bfloat16 g_w1hi[(size_t)3 * C_ * C_];
__device__ __nv_bfloat16 g_w1lo[(size_t)3 * C_ * C_];
__device__ __nv_bfloat16 g_w2hi[(size_t)C_ * C_];
__device__ __nv_bfloat16 g_w2lo[(size_t)C_ * C_];
__device__ __nv_bfloat16 g_qkvhi[(size_t)B_ * T_ * 3 * C_];
__device__ __nv_bfloat16 g_qkvlo[(size_t)B_ * T_ * 3 * C_];

// ---------------------------------------------------------------------------
// helpers
// ---------------------------------------------------------------------------
__device__ __forceinline__ uint32_t smem_u32(const void* p) {
    uint32_t a;
    asm("{ .reg .u64 t; cvta.to.shared.u64 t, %1; cvt.u32.u64 %0, t; }" : "=r"(a) : "l"(p));
    return a;
}
__device__ __forceinline__ void cp16(uint32_t dst, const void* src) {
    asm volatile("cp.async.ca.shared.global [%0], [%1], 16;" :: "r"(dst), "l"(src));
}
__device__ __forceinline__ void mma_bf16(float* c, const uint32_t* a, const uint32_t* b) {
    asm volatile(
        "mma.sync.aligned.m16n8k16.row.col.f32.bf16.bf16.f32 "
        "{%0,%1,%2,%3}, {%4,%5,%6,%7}, {%8,%9}, {%0,%1,%2,%3};"
        : "+f"(c[0]), "+f"(c[1]), "+f"(c[2]), "+f"(c[3])
        : "r"(a[0]), "r"(a[1]), "r"(a[2]), "r"(a[3]), "r"(b[0]), "r"(b[1]));
}
__device__ __forceinline__ void ldsm4(uint32_t* r, uint32_t addr) {
    asm volatile("ldmatrix.sync.aligned.m8n8.x4.shared.b16 {%0,%1,%2,%3}, [%4];"
                 : "=r"(r[0]), "=r"(r[1]), "=r"(r[2]), "=r"(r[3]) : "r"(addr));
}
__device__ __forceinline__ void ldsm4t(uint32_t* r, uint32_t addr) {
    asm volatile("ldmatrix.sync.aligned.m8n8.x4.trans.shared.b16 {%0,%1,%2,%3}, [%4];"
                 : "=r"(r[0]), "=r"(r[1]), "=r"(r[2]), "=r"(r[3]) : "r"(addr));
}

// ---------------------------------------------------------------------------
// fp32 -> (hi, lo) bf16 split
// ---------------------------------------------------------------------------
__global__ __launch_bounds__(256) void split_bf16(const float* __restrict__ in,
                                                  __nv_bfloat16* __restrict__ hi,
                                                  __nv_bfloat16* __restrict__ lo,
                                                  int n4) {
    int i = blockIdx.x * blockDim.x + threadIdx.x;
    if (i >= n4) return;
    float4 v = ((const float4*)in)[i];
    __nv_bfloat16 h0 = __float2bfloat16_rn(v.x);
    __nv_bfloat16 h1 = __float2bfloat16_rn(v.y);
    __nv_bfloat16 h2 = __float2bfloat16_rn(v.z);
    __nv_bfloat16 h3 = __float2bfloat16_rn(v.w);
    __nv_bfloat16 l0 = __float2bfloat16_rn(v.x - __bfloat162float(h0));
    __nv_bfloat16 l1 = __float2bfloat16_rn(v.y - __bfloat162float(h1));
    __nv_bfloat16 l2 = __float2bfloat16_rn(v.z - __bfloat162float(h2));
    __nv_bfloat16 l3 = __float2bfloat16_rn(v.w - __bfloat162float(h3));
    __nv_bfloat162* hp = (__nv_bfloat162*)hi;
    __nv_bfloat162* lp = (__nv_bfloat162*)lo;
    hp[2 * i] = __halves2bfloat162(h0, h1);
    hp[2 * i + 1] = __halves2bfloat162(h2, h3);
    lp[2 * i] = __halves2bfloat162(l0, l1);
    lp[2 * i + 1] = __halves2bfloat162(l2, l3);
}

// ---------------------------------------------------------------------------
// 3-term split-bf16 GEMM (unchanged from R11 passing kernel)
// ---------------------------------------------------------------------------
__global__ __launch_bounds__(256, 2) void gemm_split(const __nv_bfloat16* __restrict__ Ahi,
                                                     const __nv_bfloat16* __restrict__ Alo,
                                                     const __nv_bfloat16* __restrict__ Bhi,
                                                     const __nv_bfloat16* __restrict__ Blo,
                                                     float* __restrict__ Cm, int N) {
    extern __shared__ __align__(1024) uint32_t sw[];
    const int tid = threadIdx.x;
    const int wid = tid >> 5, lane = tid & 31;
    const int warp_m = wid >> 2, warp_n = wid & 3;
    const int gr = lane >> 2, lk = lane & 3;
    const int m0 = blockIdx.y * 128, n0 = blockIdx.x * 128;

    const int ldrow = tid >> 1, half = tid & 1;
    const long gofs = (long)ldrow * GK + half * 16;
    const __nv_bfloat16* srcs[4] = {Ahi + (long)m0 * GK + gofs, Alo + (long)m0 * GK + gofs,
                                    Bhi + (long)n0 * GK + gofs, Blo + (long)n0 * GK + gofs};
    const uint32_t sbase = smem_u32(sw);
    const uint32_t drow = (uint32_t)ldrow * (PW * 4) + (uint32_t)half * 32;

    const uint32_t aoff = (uint32_t)(warp_m * 64 + (lane & 15)) * (PW * 4) + ((uint32_t)(lane >> 4) << 4);
    const uint32_t boff = (uint32_t)(warp_n * 32 + ((lane >> 4) & 1) * 8 + (lane & 7)) * (PW * 4)
                          + (((uint32_t)(lane >> 3) & 1) << 4);

    float acc[4][4][4];
#pragma unroll
    for (int mt = 0; mt < 4; mt++)
#pragma unroll
        for (int nt = 0; nt < 4; nt++)
#pragma unroll
            for (int i = 0; i < 4; i++) acc[mt][nt][i] = 0.f;

#pragma unroll
    for (int t = 0; t < 4; t++) {
        const uint32_t d = sbase + (uint32_t)t * (TILE_W * 4) + drow;
        cp16(d, srcs[t]);
        cp16(d + 16, srcs[t] + 8);
    }
    asm volatile("cp.async.commit_group;" ::: "memory");

    for (int c = 0; c < NCHUNK; ++c) {
        if (c + 1 < NCHUNK) {
            const uint32_t bo = (uint32_t)((c + 1) & 1) * (BUF_W * 4);
#pragma unroll
            for (int t = 0; t < 4; t++) {
                const uint32_t d = sbase + bo + (uint32_t)t * (TILE_W * 4) + drow;
                const __nv_bfloat16* s = srcs[t] + (c + 1) * CHUNK;
                cp16(d, s);
                cp16(d + 16, s + 8);
            }
            asm volatile("cp.async.commit_group;" ::: "memory");
            asm volatile("cp.async.wait_group 1;" ::: "memory");
        } else {
            asm volatile("cp.async.wait_group 0;" ::: "memory");
        }
        __syncthreads();

        const uint32_t bufb = sbase + (uint32_t)(c & 1) * (BUF_W * 4);
        const uint32_t ah_b = bufb + aoff;
        const uint32_t al_b = bufb + TILE_W * 4 + aoff;
        const uint32_t bh_b = bufb + 2 * TILE_W * 4 + boff;
        const uint32_t bl_b = bufb + 3 * TILE_W * 4 + boff;
#pragma unroll
        for (int s = 0; s < 2; s++) {
            const uint32_t ks = (uint32_t)s * 32u;
            uint32_t ah[4][4], al[4][4], bh[2][4], bl[2][4];
#pragma unroll
            for (int mt = 0; mt < 4; mt++) ldsm4(ah[mt], ah_b + (uint32_t)mt * (16 * PW * 4) + ks);
#pragma unroll
            for (int p = 0; p < 2; p++) ldsm4(bh[p], bh_b + (uint32_t)p * (16 * PW * 4) + ks);
#pragma unroll
            for (int mt = 0; mt < 4; mt++)
#pragma unroll
                for (int nt = 0; nt < 4; nt++)
                    mma_bf16(acc[mt][nt], ah[mt], &bh[nt >> 1][(nt & 1) * 2]);
#pragma unroll
            for (int p = 0; p < 2; p++) ldsm4(bl[p], bl_b + (uint32_t)p * (16 * PW * 4) + ks);
#pragma unroll
            for (int mt = 0; mt < 4; mt++)
#pragma unroll
                for (int nt = 0; nt < 4; nt++)
                    mma_bf16(acc[mt][nt], ah[mt], &bl[nt >> 1][(nt & 1) * 2]);
#pragma unroll
            for (int mt = 0; mt < 4; mt++) ldsm4(al[mt], al_b + (uint32_t)mt * (16 * PW * 4) + ks);
#pragma unroll
            for (int mt = 0; mt < 4; mt++)
#pragma unroll
                for (int nt = 0; nt < 4; nt++)
                    mma_bf16(acc[mt][nt], al[mt], &bh[nt >> 1][(nt & 1) * 2]);
        }
        __syncthreads();
    }

#pragma unroll
    for (int mt = 0; mt < 4; mt++) {
        const int m = m0 + warp_m * 64 + mt * 16 + gr;
#pragma unroll
        for (int nt = 0; nt < 4; nt++) {
            const int n = n0 + warp_n * 32 + nt * 8 + 2 * lk;
            *(float2*)&Cm[(long)m * N + n] = make_float2(acc[mt][nt][0], acc[mt][nt][1]);
            *(float2*)&Cm[(long)(m + 8) * N + n] = make_float2(acc[mt][nt][2], acc[mt][nt][3]);
        }
    }
}

// ---------------------------------------------------------------------------
// Tensor-core sliding-window attention (FA2 style, split-bf16 3-term MMA).
// CTA: 64 queries x (b,h). 4 warps, warp = 16 q rows x all 64 keys.
// smem (bytes): Qhi[0,9216) Qlo[9216,18432)
//   stage s in {0,1} at 18432+s*36864: Khi,Klo,Vhi,Vlo each 9216.
// Tile layout: 64 rows x 64 bf16, row pitch 144B (36 words) - ldmatrix
// conflict-free for both normal and trans.
// ---------------------------------------------------------------------------
#define APITCH 144
#define ATB 9216
#define ASTAGE0 18432
#define ASTAGE_SZ (4 * ATB)
#define ATT_SMEM (ASTAGE0 + 2 * ASTAGE_SZ)

__global__ __launch_bounds__(128) void attn_mma(const __nv_bfloat16* __restrict__ qhi,
                                                const __nv_bfloat16* __restrict__ qlo,
                                                float* __restrict__ yatt) {
    extern __shared__ __align__(1024) unsigned char asm_[];
    const uint32_t sb = smem_u32(asm_);
    const int qt = blockIdx.x, h = blockIdx.y, b = blockIdx.z;
    const int q0 = qt * 64;
    const int tid = threadIdx.x;
    const int warp = tid >> 5, lane = tid & 31;
    const int gr = lane >> 2, lk = lane & 3;

    // ---- async load Q (hi+lo) ----
#pragma unroll
    for (int g = tid; g < 512; g += 128) {
        const int r = g >> 3, c8 = (g & 7);
        const long go = ((long)(b * T_ + q0 + r)) * (3 * C_) + h * D_ + c8 * 8;
        const uint32_t d = sb + (uint32_t)r * APITCH + (uint32_t)c8 * 16;
        cp16(d, qhi + go);
        cp16(d + ATB, qlo + go);
    }
    // stage 0: first key tile
    const int kt0 = (qt >= 4) ? (qt - 4) : 0;
    {
#pragma unroll
        for (int g = tid; g < 512; g += 128) {
            const int r = g >> 3, c8 = (g & 7);
            const long gk = ((long)(b * T_ + kt0 * 64 + r)) * (3 * C_) + C_ + h * D_ + c8 * 8;
            const uint32_t d = sb + ASTAGE0 + (uint32_t)r * APITCH + (uint32_t)c8 * 16;
            cp16(d, qhi + gk);             // Khi
            cp16(d + ATB, qlo + gk);       // Klo
            cp16(d + 2 * ATB, qhi + gk + C_);  // Vhi
            cp16(d + 3 * ATB, qlo + gk + C_);  // Vlo
        }
    }
    asm volatile("cp.async.commit_group;" ::: "memory");

    // ldmatrix lane offsets
    const uint32_t aq = sb + (uint32_t)(warp * 16 + (lane & 15)) * APITCH + ((uint32_t)(lane >> 4) << 4);
    const uint32_t bk_off = (uint32_t)(((lane >> 4) & 1) * 8 + (lane & 7)) * APITCH + (((uint32_t)(lane >> 3) & 1) << 4);
    const uint32_t bv_off = (uint32_t)((lane & 7) + ((lane >> 3) & 1) * 8) * APITCH + ((uint32_t)(lane >> 4) << 4);

    float o[8][4];
#pragma unroll
    for (int i = 0; i < 8; i++)
#pragma unroll
        for (int j = 0; j < 4; j++) o[i][j] = 0.f;
    float m0 = -1e30f, m1 = -1e30f, l0 = 0.f, l1 = 0.f;

    for (int kt = kt0; kt <= qt; kt++) {
        const uint32_t stg = sb + ASTAGE0 + (uint32_t)((kt - kt0) & 1) * ASTAGE_SZ;
        if (kt < qt) {
            const uint32_t nst = sb + ASTAGE0 + (uint32_t)((kt + 1 - kt0) & 1) * ASTAGE_SZ;
#pragma unroll
            for (int g = tid; g < 512; g += 128) {
                const int r = g >> 3, c8 = (g & 7);
                const long gk = ((long)(b * T_ + (kt + 1) * 64 + r)) * (3 * C_) + C_ + h * D_ + c8 * 8;
                const uint32_t d = nst + (uint32_t)r * APITCH + (uint32_t)c8 * 16;
                cp16(d, qhi + gk);
                cp16(d + ATB, qlo + gk);
                cp16(d + 2 * ATB, qhi + gk + C_);
                cp16(d + 3 * ATB, qlo + gk + C_);
            }
            asm volatile("cp.async.commit_group;" ::: "memory");
            asm volatile("cp.async.wait_group 1;" ::: "memory");
        } else {
            asm volatile("cp.async.wait_group 0;" ::: "memory");
        }
        __syncthreads();

        // ---- S = Q K^T (3-term split) ----
        float sc[8][4];
#pragma unroll
        for (int i = 0; i < 8; i++)
#pragma unroll
            for (int j = 0; j < 4; j++) sc[i][j] = 0.f;
        const uint32_t bk = stg + bk_off;
#pragma unroll
        for (int ks = 0; ks < 4; ks++) {
            uint32_t qh[4], ql[4];
            ldsm4(qh, aq + ks * 32);
            ldsm4(ql, aq + ATB + ks * 32);
#pragma unroll
            for (int p = 0; p < 4; p++) {
                uint32_t kh[4], kl[4];
                ldsm4(kh, bk + (uint32_t)p * (16 * APITCH) + ks * 32);
                mma_bf16(sc[2 * p], qh, kh);
                mma_bf16(sc[2 * p + 1], qh, kh + 2);
                ldsm4(kl, bk + ATB + (uint32_t)p * (16 * APITCH) + ks * 32);
                mma_bf16(sc[2 * p], qh, kl);
                mma_bf16(sc[2 * p + 1], qh, kl + 2);
                mma_bf16(sc[2 * p], ql, kh);
                mma_bf16(sc[2 * p + 1], ql, kh + 2);
            }
        }

        // ---- scale + mask ----
        const int qa = q0 + warp * 16 + gr;
        const int qb = qa + 8;
#pragma unroll
        for (int nt = 0; nt < 8; nt++) {
            const int j0 = kt * 64 + nt * 8 + 2 * lk;
#pragma unroll
            for (int i = 0; i < 4; i++) {
                const int q = (i >= 2) ? qb : qa;
                const int j = j0 + (i & 1);
                const float s = sc[nt][i] * 0.125f;
                sc[nt][i] = (j <= q && j > q - WIN_) ? s : -1e30f;
            }
        }

        // ---- online softmax (rows qa, qb) ----
        float mx0 = -1e30f, mx1 = -1e30f;
#pragma unroll
        for (int nt = 0; nt < 8; nt++) {
            mx0 = fmaxf(mx0, fmaxf(sc[nt][0], sc[nt][1]));
            mx1 = fmaxf(mx1, fmaxf(sc[nt][2], sc[nt][3]));
        }
        mx0 = fmaxf(mx0, __shfl_xor_sync(0xffffffffu, mx0, 1));
        mx0 = fmaxf(mx0, __shfl_xor_sync(0xffffffffu, mx0, 2));
        mx1 = fmaxf(mx1, __shfl_xor_sync(0xffffffffu, mx1, 1));
        mx1 = fmaxf(mx1, __shfl_xor_sync(0xffffffffu, mx1, 2));
        const float mn0 = fmaxf(m0, mx0), mn1 = fmaxf(m1, mx1);
        const float cr0 = __expf(m0 - mn0), cr1 = __expf(m1 - mn1);
        m0 = mn0; m1 = mn1;
        float s0 = 0.f, s1 = 0.f;
#pragma unroll
        for (int nt = 0; nt < 8; nt++) {
            sc[nt][0] = __expf(sc[nt][0] - mn0);
            sc[nt][1] = __expf(sc[nt][1] - mn0);
            sc[nt][2] = __expf(sc[nt][2] - mn1);
            sc[nt][3] = __expf(sc[nt][3] - mn1);
            s0 += sc[nt][0] + sc[nt][1];
            s1 += sc[nt][2] + sc[nt][3];
        }
        s0 += __shfl_xor_sync(0xffffffffu, s0, 1);
        s0 += __shfl_xor_sync(0xffffffffu, s0, 2);
        s1 += __shfl_xor_sync(0xffffffffu, s1, 1);
        s1 += __shfl_xor_sync(0xffffffffu, s1, 2);
        l0 = l0 * cr0 + s0;
        l1 = l1 * cr1 + s1;
#pragma unroll
        for (int dt = 0; dt < 8; dt++) {
            o[dt][0] *= cr0; o[dt][1] *= cr0;
            o[dt][2] *= cr1; o[dt][3] *= cr1;
        }

        // ---- O += P V (3-term split) ----
        const uint32_t bv = stg + 2 * ATB + bv_off;
#pragma unroll
        for (int ks = 0; ks < 4; ks++) {
            uint32_t ph[4], pl[4];
#pragma unroll
            for (int half = 0; half < 2; half++) {
                const float p0 = sc[2 * ks + half][0], p1 = sc[2 * ks + half][1];
                const float p2 = sc[2 * ks + half][2], p3 = sc[2 * ks + half][3];
                __nv_bfloat162 hA = __floats2bfloat162_rn(p0, p1);
                __nv_bfloat162 hB = __floats2bfloat162_rn(p2, p3);
                ph[2 * half] = *(uint32_t*)&hA;
                ph[2 * half + 1] = *(uint32_t*)&hB;
                __nv_bfloat162 lA = __floats2bfloat162_rn(p0 - __low2float(hA), p1 - __high2float(hA));
                __nv_bfloat162 lB = __floats2bfloat162_rn(p2 - __low2float(hB), p3 - __high2float(hB));
                pl[2 * half] = *(uint32_t*)&lA;
                pl[2 * half + 1] = *(uint32_t*)&lB;
            }
            // fragment order: a0=tile2ks rows gr, a1=tile2ks rows gr+8, a2=tile2ks+1 ...
            uint32_t af[4] = {ph[0], ph[1], ph[2], ph[3]};
            uint32_t afl[4] = {pl[0], pl[1], pl[2], pl[3]};
#pragma unroll
            for (int p = 0; p < 4; p++) {
                uint32_t vh[4], vl[4];
                ldsm4t(vh, bv + (uint32_t)ks * (16 * APITCH) + (uint32_t)p * 32);
                mma_bf16(o[2 * p], af, vh);
                mma_bf16(o[2 * p + 1], af, vh + 2);
                ldsm4t(vl, bv + ATB + (uint32_t)ks * (16 * APITCH) + (uint32_t)p * 32);
                mma_bf16(o[2 * p], af, vl);
                mma_bf16(o[2 * p + 1], af, vl + 2);
                mma_bf16(o[2 * p], afl, vh);
                mma_bf16(o[2 * p + 1], afl, vh + 2);
            }
        }
        __syncthreads();
    }

    // ---- normalize + store ----
    const float i0 = 1.f / l0, i1 = 1.f / l1;
    const int qa = q0 + warp * 16 + gr;
#pragma unroll
    for (int dt = 0; dt < 8; dt++) {
        const int col = h * D_ + dt * 8 + 2 * lk;
        *(float2*)&yatt[((long)(b * T_ + qa)) * C_ + col] = make_float2(o[dt][0] * i0, o[dt][1] * i0);
        *(float2*)&yatt[((long)(b * T_ + qa + 8)) * C_ + col] = make_float2(o[dt][2] * i1, o[dt][3] * i1);
    }
}

// ---------------------------------------------------------------------------
extern "C" void kernel_launch(void* const* d_in, const int* in_sizes, int n_in,
                              void* d_out, int out_size) {
    const float* x     = (const float*)d_in[0];  // [B,T,C]
    const float* Wqkv  = (const float*)d_in[1];  // [3C, C]
    const float* Wproj = (const float*)d_in[2];  // [C, C]
    float* out = (float*)d_out;                  // [B,T,C]

    float *qkv, *att;
    __nv_bfloat16 *xhi, *xlo, *ahi, *alo, *w1hi, *w1lo, *w2hi, *w2lo, *qvh, *qvl;
    cudaGetSymbolAddress((void**)&qkv, g_qkv);
    cudaGetSymbolAddress((void**)&att, g_att);
    cudaGetSymbolAddress((void**)&xhi, g_xhi);
    cudaGetSymbolAddress((void**)&xlo, g_xlo);
    cudaGetSymbolAddress((void**)&ahi, g_ahi);
    cudaGetSymbolAddress((void**)&alo, g_alo);
    cudaGetSymbolAddress((void**)&w1hi, g_w1hi);
    cudaGetSymbolAddress((void**)&w1lo, g_w1lo);
    cudaGetSymbolAddress((void**)&w2hi, g_w2hi);
    cudaGetSymbolAddress((void**)&w2lo, g_w2lo);
    cudaGetSymbolAddress((void**)&qvh, g_qkvhi);
    cudaGetSymbolAddress((void**)&qvl, g_qkvlo);

    const int M = B_ * T_;  // 8192
    cudaFuncSetAttribute(gemm_split, cudaFuncAttributeMaxDynamicSharedMemorySize, GEMM_SMEM);
    cudaFuncSetAttribute(attn_mma, cudaFuncAttributeMaxDynamicSharedMemorySize, ATT_SMEM);

    // 0) split inputs into bf16 hi/lo planes
    {
        int nx = M * C_ / 4;
        split_bf16<<<(nx + 255) / 256, 256>>>(x, xhi, xlo, nx);
        int nw1 = 3 * C_ * C_ / 4;
        split_bf16<<<(nw1 + 255) / 256, 256>>>(Wqkv, w1hi, w1lo, nw1);
        int nw2 = C_ * C_ / 4;
        split_bf16<<<(nw2 + 255) / 256, 256>>>(Wproj, w2hi, w2lo, nw2);
    }

    // 1) qkv = x @ Wqkv^T   [8192, 3072]
    {
        dim3 grid(3 * C_ / 128, M / 128);
        gemm_split<<<grid, 256, GEMM_SMEM>>>(xhi, xlo, w1hi, w1lo, qkv, 3 * C_);
    }

    // 1b) split qkv into hi/lo planes for attention
    {
        int nq = M * 3 * C_ / 4;
        split_bf16<<<(nq + 255) / 256, 256>>>(qkv, qvh, qvl, nq);
    }

    // 2) tensor-core windowed attention -> att [8192, 1024]
    {
        dim3 grid(T_ / 64, H_, B_);
        attn_mma<<<grid, 128, ATT_SMEM>>>(qvh, qvl, att);
    }

    // 2b) split attention output
    {
        int na = M * C_ / 4;
        split_bf16<<<(na + 255) / 256, 256>>>(att, ahi, alo, na);
    }

    // 3) out = att @ Wproj^T  [8192, 1024]
    {
        dim3 grid(C_ / 128, M / 128);
        gemm_split<<<grid, 256, GEMM_SMEM>>>(ahi, alo, w2hi, w2lo, out, C_);
    }
}